// round 2
// baseline (speedup 1.0000x reference)
#include <cuda_runtime.h>
#include <cstdint>

#define N_NODES 40000
#define N_EDGES 640000
#define IN_CH   128
#define OUT_CH  128
#define NUM_RBF 64

// Scratch for h = x @ Wl + bl  (20.48 MB, static device array — no allocs)
__device__ float g_h[(size_t)N_NODES * OUT_CH];

// ---------------------------------------------------------------------------
// red.global.add.v4.f32 — vectorized no-return atomic (sm_90+)
// ---------------------------------------------------------------------------
__device__ __forceinline__ void red_add_v4(float* addr, float4 v) {
    asm volatile("red.global.add.v4.f32 [%0], {%1,%2,%3,%4};"
                 :: "l"(addr), "f"(v.x), "f"(v.y), "f"(v.z), "f"(v.w)
                 : "memory");
}

// ---------------------------------------------------------------------------
// 8x8 register-tile GEMM inner step: processes 4 k-values from smem tiles.
// ---------------------------------------------------------------------------
__device__ __forceinline__ void ftile_step4(const float* sA, int lda,
                                            const float* sB, int ldb,
                                            int rb, int cb, int k,
                                            float acc[8][8]) {
    float4 a4[8];
#pragma unroll
    for (int i = 0; i < 8; i++)
        a4[i] = *(const float4*)(sA + (rb + i) * lda + k);
#pragma unroll
    for (int kk = 0; kk < 4; kk++) {
        const float* bp = sB + (k + kk) * ldb + cb;
        float4 b0 = *(const float4*)(bp);
        float4 b1 = *(const float4*)(bp + 4);
        float bv[8] = {b0.x, b0.y, b0.z, b0.w, b1.x, b1.y, b1.z, b1.w};
#pragma unroll
        for (int i = 0; i < 8; i++) {
            float av = (kk == 0) ? a4[i].x : (kk == 1) ? a4[i].y
                     : (kk == 2) ? a4[i].z : a4[i].w;
#pragma unroll
            for (int j = 0; j < 8; j++)
                acc[i][j] = fmaf(av, bv[j], acc[i][j]);
        }
    }
}

// ---------------------------------------------------------------------------
// Kernel 1: h = x @ Wl + bl.   Block: 128 rows x 128 cols, 256 threads.
// ---------------------------------------------------------------------------
__global__ void __launch_bounds__(256)
node_linear_kernel(const float* __restrict__ x,
                   const float* __restrict__ Wl,
                   const float* __restrict__ bl,
                   float* __restrict__ h) {
    __shared__ float s_x[128 * 20];
    __shared__ float s_w[16 * 132];

    const int tid = threadIdx.x;
    const int m0  = blockIdx.x * 128;
    const int tx  = tid & 15, ty = tid >> 4;
    const int rb  = ty * 8,  cb = tx * 8;

    float acc[8][8];
#pragma unroll
    for (int i = 0; i < 8; i++)
#pragma unroll
        for (int j = 0; j < 8; j++) acc[i][j] = 0.f;

    for (int k0 = 0; k0 < IN_CH; k0 += 16) {
        for (int i = tid; i < 512; i += 256) {
            int r = i >> 2, q = i & 3;
            float4 v = make_float4(0.f, 0.f, 0.f, 0.f);
            if (m0 + r < N_NODES)
                v = *(const float4*)(x + (size_t)(m0 + r) * IN_CH + k0 + q * 4);
            *(float4*)(s_x + r * 20 + q * 4) = v;
        }
        for (int i = tid; i < 512; i += 256) {
            int r = i >> 5, q = i & 31;
            *(float4*)(s_w + r * 132 + q * 4) =
                *(const float4*)(Wl + (size_t)(k0 + r) * OUT_CH + q * 4);
        }
        __syncthreads();
#pragma unroll 1
        for (int k = 0; k < 16; k += 4)
            ftile_step4(s_x, 20, s_w, 132, rb, cb, k, acc);
        __syncthreads();
    }

    float bj[8];
#pragma unroll
    for (int j = 0; j < 8; j++) bj[j] = bl[cb + j];
#pragma unroll
    for (int i = 0; i < 8; i++) {
        int row = m0 + rb + i;
        if (row < N_NODES) {
            float4 v0 = make_float4(acc[i][0] + bj[0], acc[i][1] + bj[1],
                                    acc[i][2] + bj[2], acc[i][3] + bj[3]);
            float4 v1 = make_float4(acc[i][4] + bj[4], acc[i][5] + bj[5],
                                    acc[i][6] + bj[6], acc[i][7] + bj[7]);
            *(float4*)(h + (size_t)row * OUT_CH + cb)     = v0;
            *(float4*)(h + (size_t)row * OUT_CH + cb + 4) = v1;
        }
    }
}

// ---------------------------------------------------------------------------
// Kernel 2: fused edge MLP + gather-modulate-scatter.
// 128 edges / block, 256 threads, ~200 KB dynamic smem (1 CTA/SM).
// ---------------------------------------------------------------------------
#define S_RBF_LEN (128 * 68)
#define S_W1_LEN  (64 * 132)
#define S_W2_LEN  (128 * 132)
#define S_H_LEN   (128 * 132)
#define EDGE_SMEM_FLOATS (S_RBF_LEN + S_W1_LEN + S_W2_LEN + S_H_LEN + 256)
#define EDGE_SMEM_BYTES  (EDGE_SMEM_FLOATS * 4)

__global__ void __launch_bounds__(256)
edge_kernel(const float* __restrict__ rbf,
            const int* __restrict__ eidx,          // int32! (JAX x64 disabled)
            const float* __restrict__ W1, const float* __restrict__ b1,
            const float* __restrict__ W2, const float* __restrict__ b2,
            const float* __restrict__ h,
            float* __restrict__ out) {
    extern __shared__ float sm[];
    float* s_rbf = sm;
    float* s_W1  = s_rbf + S_RBF_LEN;
    float* s_W2  = s_W1 + S_W1_LEN;
    float* s_H   = s_W2 + S_W2_LEN;
    int*   s_dst = (int*)(s_H + S_H_LEN);
    int*   s_src = s_dst + 128;

    const int tid = threadIdx.x;
    const size_t e0 = (size_t)blockIdx.x * 128;

    if (tid < 128) {
        int d = eidx[e0 + tid];                     // row = destination
        int s = eidx[(size_t)N_EDGES + e0 + tid];   // col = source
        // defensive clamp: dtype surprises show as rel_err, not IMA
        s_dst[tid] = min(max(d, 0), N_NODES - 1);
        s_src[tid] = min(max(s, 0), N_NODES - 1);
    }
    for (int i = tid; i < 128 * 16; i += 256) {
        int r = i >> 4, q = i & 15;
        *(float4*)(s_rbf + r * 68 + q * 4) =
            *(const float4*)(rbf + (e0 + r) * NUM_RBF + q * 4);
    }
    for (int i = tid; i < 64 * 32; i += 256) {
        int r = i >> 5, q = i & 31;
        *(float4*)(s_W1 + r * 132 + q * 4) =
            *(const float4*)(W1 + (size_t)r * OUT_CH + q * 4);
    }
    for (int i = tid; i < 128 * 32; i += 256) {
        int r = i >> 5, q = i & 31;
        *(float4*)(s_W2 + r * 132 + q * 4) =
            *(const float4*)(W2 + (size_t)r * OUT_CH + q * 4);
    }
    __syncthreads();

    const int tx = tid & 15, ty = tid >> 4;
    const int rb = ty * 8,  cb = tx * 8;
    float acc[8][8];

    // -------- Phase 1: H = relu(RBF @ W1 + b1) --------
#pragma unroll
    for (int j = 0; j < 8; j++) {
        float bv = b1[cb + j];
#pragma unroll
        for (int i = 0; i < 8; i++) acc[i][j] = bv;
    }
#pragma unroll 1
    for (int k = 0; k < NUM_RBF; k += 4)
        ftile_step4(s_rbf, 68, s_W1, 132, rb, cb, k, acc);
#pragma unroll
    for (int i = 0; i < 8; i++) {
#pragma unroll
        for (int j = 0; j < 8; j++) acc[i][j] = fmaxf(acc[i][j], 0.f);
        *(float4*)(s_H + (rb + i) * 132 + cb) =
            make_float4(acc[i][0], acc[i][1], acc[i][2], acc[i][3]);
        *(float4*)(s_H + (rb + i) * 132 + cb + 4) =
            make_float4(acc[i][4], acc[i][5], acc[i][6], acc[i][7]);
    }
    __syncthreads();

    // -------- Phase 2: Wt = H @ W2 + b2 --------
#pragma unroll
    for (int j = 0; j < 8; j++) {
        float bv = b2[cb + j];
#pragma unroll
        for (int i = 0; i < 8; i++) acc[i][j] = bv;
    }
#pragma unroll 1
    for (int k = 0; k < OUT_CH; k += 4)
        ftile_step4(s_H, 132, s_W2, 132, rb, cb, k, acc);
    __syncthreads();

#pragma unroll
    for (int i = 0; i < 8; i++) {
        *(float4*)(s_H + (rb + i) * 132 + cb) =
            make_float4(acc[i][0], acc[i][1], acc[i][2], acc[i][3]);
        *(float4*)(s_H + (rb + i) * 132 + cb + 4) =
            make_float4(acc[i][4], acc[i][5], acc[i][6], acc[i][7]);
    }
    __syncthreads();

    // -------- Phase 3: msg = h[src] * Wt; scatter-add to out[dst] --------
    const int warp = tid >> 5, lane = tid & 31;
#pragma unroll 1
    for (int t = 0; t < 16; t++) {
        int e = warp * 16 + t;
        int src = s_src[e], dst = s_dst[e];
        float4 hv = *(const float4*)(h + (size_t)src * OUT_CH + lane * 4);
        float4 wv = *(const float4*)(s_H + e * 132 + lane * 4);
        float4 m = make_float4(hv.x * wv.x, hv.y * wv.y, hv.z * wv.z, hv.w * wv.w);
        red_add_v4(out + (size_t)dst * OUT_CH + lane * 4, m);
    }
}

// ---------------------------------------------------------------------------
extern "C" void kernel_launch(void* const* d_in, const int* in_sizes, int n_in,
                              void* d_out, int out_size) {
    const float* x    = (const float*)d_in[0];
    const int*   eidx = (const int*)d_in[1];      // int32 per harness dtype rules
    const float* rbf  = (const float*)d_in[2];
    const float* W1   = (const float*)d_in[3];
    const float* b1   = (const float*)d_in[4];
    const float* W2   = (const float*)d_in[5];
    const float* b2   = (const float*)d_in[6];
    const float* Wl   = (const float*)d_in[7];
    const float* bl   = (const float*)d_in[8];
    float* out = (float*)d_out;

    float* h_ptr = nullptr;
    cudaGetSymbolAddress((void**)&h_ptr, g_h);

    cudaFuncSetAttribute(edge_kernel,
                         cudaFuncAttributeMaxDynamicSharedMemorySize,
                         EDGE_SMEM_BYTES);

    cudaMemsetAsync(d_out, 0, (size_t)N_NODES * OUT_CH * sizeof(float), 0);

    node_linear_kernel<<<(N_NODES + 127) / 128, 256>>>(x, Wl, bl, h_ptr);
    edge_kernel<<<N_EDGES / 128, 256, EDGE_SMEM_BYTES>>>(rbf, eidx, W1, b1,
                                                         W2, b2, h_ptr, out);
}

// round 4
// speedup vs baseline: 2.5618x; 2.5618x over previous
#include <cuda_runtime.h>
#include <cstdint>

#define N_NODES 40000
#define N_EDGES 640000
#define IN_CH   128
#define OUT_CH  128
#define NUM_RBF 64
#define TILE    128
#define N_TILES (N_EDGES / TILE)

// ---------------- device scratch (no allocs allowed) ----------------
__device__ float g_h[(size_t)N_NODES * OUT_CH];      // x @ Wl + bl

// ---------------- helpers ----------------
__device__ __forceinline__ float rnd_tf32(float x) {
    float r;
    asm("cvt.rna.tf32.f32 %0, %1;" : "=f"(r) : "f"(x));
    return r;
}
__device__ __forceinline__ uint32_t tf32_bits(float x) {
    return __float_as_uint(rnd_tf32(x));
}
__device__ __forceinline__ void red_add_v4(float* addr, float4 v) {
    asm volatile("red.global.add.v4.f32 [%0], {%1,%2,%3,%4};"
                 :: "l"(addr), "f"(v.x), "f"(v.y), "f"(v.z), "f"(v.w) : "memory");
}
// mma.sync m16n8k8 tf32 (baseline PTX, sm_80+; lowers to HMMA on sm_103)
__device__ __forceinline__ void mma_tf32(float d[4], const uint32_t a[4],
                                         const uint32_t b[2]) {
    asm volatile(
        "mma.sync.aligned.m16n8k8.row.col.f32.tf32.tf32.f32 "
        "{%0,%1,%2,%3}, {%4,%5,%6,%7}, {%8,%9}, {%0,%1,%2,%3};"
        : "+f"(d[0]), "+f"(d[1]), "+f"(d[2]), "+f"(d[3])
        : "r"(a[0]), "r"(a[1]), "r"(a[2]), "r"(a[3]), "r"(b[0]), "r"(b[1]));
}

// ---------------------------------------------------------------------------
// node linear (fp32 register-tiled, proven in R2)
// ---------------------------------------------------------------------------
__device__ __forceinline__ void ftile_step4(const float* sA, int lda,
                                            const float* sB, int ldb,
                                            int rb, int cb, int k,
                                            float acc[8][8]) {
    float4 a4[8];
#pragma unroll
    for (int i = 0; i < 8; i++)
        a4[i] = *(const float4*)(sA + (rb + i) * lda + k);
#pragma unroll
    for (int kk = 0; kk < 4; kk++) {
        const float* bp = sB + (k + kk) * ldb + cb;
        float4 b0 = *(const float4*)(bp);
        float4 b1 = *(const float4*)(bp + 4);
        float bv[8] = {b0.x, b0.y, b0.z, b0.w, b1.x, b1.y, b1.z, b1.w};
#pragma unroll
        for (int i = 0; i < 8; i++) {
            float av = (kk == 0) ? a4[i].x : (kk == 1) ? a4[i].y
                     : (kk == 2) ? a4[i].z : a4[i].w;
#pragma unroll
            for (int j = 0; j < 8; j++)
                acc[i][j] = fmaf(av, bv[j], acc[i][j]);
        }
    }
}

__global__ void __launch_bounds__(256)
node_linear_kernel(const float* __restrict__ x, const float* __restrict__ Wl,
                   const float* __restrict__ bl, float* __restrict__ h) {
    __shared__ float s_x[128 * 20];
    __shared__ float s_w[16 * 132];
    const int tid = threadIdx.x;
    const int m0 = blockIdx.x * 128;
    const int tx = tid & 15, ty = tid >> 4;
    const int rb = ty * 8, cb = tx * 8;
    float acc[8][8];
#pragma unroll
    for (int i = 0; i < 8; i++)
#pragma unroll
        for (int j = 0; j < 8; j++) acc[i][j] = 0.f;

    for (int k0 = 0; k0 < IN_CH; k0 += 16) {
        for (int i = tid; i < 512; i += 256) {
            int r = i >> 2, q = i & 3;
            float4 v = make_float4(0.f, 0.f, 0.f, 0.f);
            if (m0 + r < N_NODES)
                v = *(const float4*)(x + (size_t)(m0 + r) * IN_CH + k0 + q * 4);
            *(float4*)(s_x + r * 20 + q * 4) = v;
        }
        for (int i = tid; i < 512; i += 256) {
            int r = i >> 5, q = i & 31;
            *(float4*)(s_w + r * 132 + q * 4) =
                *(const float4*)(Wl + (size_t)(k0 + r) * OUT_CH + q * 4);
        }
        __syncthreads();
#pragma unroll 1
        for (int k = 0; k < 16; k += 4)
            ftile_step4(s_x, 20, s_w, 132, rb, cb, k, acc);
        __syncthreads();
    }
    float bj[8];
#pragma unroll
    for (int j = 0; j < 8; j++) bj[j] = bl[cb + j];
#pragma unroll
    for (int i = 0; i < 8; i++) {
        int row = m0 + rb + i;
        if (row < N_NODES) {
            *(float4*)(h + (size_t)row * OUT_CH + cb) =
                make_float4(acc[i][0] + bj[0], acc[i][1] + bj[1],
                            acc[i][2] + bj[2], acc[i][3] + bj[3]);
            *(float4*)(h + (size_t)row * OUT_CH + cb + 4) =
                make_float4(acc[i][4] + bj[4], acc[i][5] + bj[5],
                            acc[i][6] + bj[6], acc[i][7] + bj[7]);
        }
    }
}

// ---------------------------------------------------------------------------
// persistent edge kernel: tf32 mma.sync MLP + gather/scatter
// 256 threads = 8 warps; warp w owns output cols [w*16, w*16+16)
// smem floats: rbf[128][68] | H[128][132] | out[128][132] | idx
// ---------------------------------------------------------------------------
#define LDR 68
#define LDH 132
#define S_RBF 0
#define S_H   (128 * LDR)                  // 8704
#define S_OUT (S_H + 128 * LDH)            // 25600
#define S_IDX (S_OUT + 128 * LDH)          // 42496
#define SM_FLOATS (S_IDX + 256)
#define SM_BYTES  (SM_FLOATS * 4)

__global__ void __launch_bounds__(256, 1)
edge_kernel_mma(const float* __restrict__ rbf, const int* __restrict__ eidx,
                const float* __restrict__ W1, const float* __restrict__ b1g,
                const float* __restrict__ W2, const float* __restrict__ b2g,
                const float* __restrict__ h, float* __restrict__ out,
                int grid_stride) {
    extern __shared__ float sm[];
    float* s_rbf = sm + S_RBF;
    float* s_H   = sm + S_H;
    float* s_out = sm + S_OUT;
    int*   s_dst = (int*)(sm + S_IDX);
    int*   s_src = s_dst + 128;

    const int tid  = threadIdx.x;
    const int wid  = tid >> 5, lane = tid & 31;
    const int g    = lane >> 2, tig = lane & 3;   // quad row / thread-in-quad
    const int nb   = wid * 16;                    // this warp's N base

    // ---- one-time: weight fragments -> registers (tf32-rounded) ----
    // B fragment (col-major KxN): b0 @(k=tig, n=g+n8base), b1 @(k=tig+4, ...)
    uint32_t b1f[8][2][2];    // [kstep][ntile][reg]
    uint32_t b2f[16][2][2];
#pragma unroll
    for (int ks = 0; ks < 8; ks++)
#pragma unroll
        for (int nt = 0; nt < 2; nt++) {
            int n = nb + nt * 8 + g;
            b1f[ks][nt][0] = tf32_bits(W1[(size_t)(ks * 8 + tig) * OUT_CH + n]);
            b1f[ks][nt][1] = tf32_bits(W1[(size_t)(ks * 8 + tig + 4) * OUT_CH + n]);
        }
#pragma unroll
    for (int ks = 0; ks < 16; ks++)
#pragma unroll
        for (int nt = 0; nt < 2; nt++) {
            int n = nb + nt * 8 + g;
            b2f[ks][nt][0] = tf32_bits(W2[(size_t)(ks * 8 + tig) * OUT_CH + n]);
            b2f[ks][nt][1] = tf32_bits(W2[(size_t)(ks * 8 + tig + 4) * OUT_CH + n]);
        }
    // biases for this thread's C columns: col = nb + nt*8 + tig*2 + {0,1}
    float bias1[4], bias2[4];
#pragma unroll
    for (int nt = 0; nt < 2; nt++)
#pragma unroll
        for (int p = 0; p < 2; p++) {
            bias1[nt * 2 + p] = b1g[nb + nt * 8 + tig * 2 + p];
            bias2[nt * 2 + p] = b2g[nb + nt * 8 + tig * 2 + p];
        }

    for (int tile = blockIdx.x; tile < N_TILES; tile += grid_stride) {
        const size_t e0 = (size_t)tile * TILE;

        if (tid < 128) {
            s_dst[tid] = eidx[e0 + tid];
            s_src[tid] = eidx[(size_t)N_EDGES + e0 + tid];
        }
        // rbf tile -> smem, tf32-rounded
        for (int i = tid; i < 128 * 16; i += 256) {
            int r = i >> 4, q = i & 15;
            float4 v = *(const float4*)(rbf + (e0 + r) * NUM_RBF + q * 4);
            v.x = rnd_tf32(v.x); v.y = rnd_tf32(v.y);
            v.z = rnd_tf32(v.z); v.w = rnd_tf32(v.w);
            *(float4*)(s_rbf + r * LDR + q * 4) = v;
        }
        __syncthreads();

        // ---- GEMM1: H = relu(RBF @ W1 + b1), K=64 ----
        {
            float acc[16][4];   // [mt*2+nt][reg]
#pragma unroll
            for (int mt = 0; mt < 8; mt++)
#pragma unroll
                for (int nt = 0; nt < 2; nt++) {
                    acc[mt * 2 + nt][0] = bias1[nt * 2];
                    acc[mt * 2 + nt][1] = bias1[nt * 2 + 1];
                    acc[mt * 2 + nt][2] = bias1[nt * 2];
                    acc[mt * 2 + nt][3] = bias1[nt * 2 + 1];
                }
#pragma unroll
            for (int ks = 0; ks < 8; ks++) {
#pragma unroll
                for (int mt = 0; mt < 8; mt++) {
                    const float* ap = s_rbf + (mt * 16 + g) * LDR + ks * 8 + tig;
                    uint32_t a[4];
                    a[0] = __float_as_uint(ap[0]);
                    a[1] = __float_as_uint(ap[8 * LDR]);
                    a[2] = __float_as_uint(ap[4]);
                    a[3] = __float_as_uint(ap[8 * LDR + 4]);
                    mma_tf32(acc[mt * 2 + 0], a, b1f[ks][0]);
                    mma_tf32(acc[mt * 2 + 1], a, b1f[ks][1]);
                }
            }
            // epilogue: relu + tf32 round -> s_H
#pragma unroll
            for (int mt = 0; mt < 8; mt++)
#pragma unroll
                for (int nt = 0; nt < 2; nt++) {
                    int col = nb + nt * 8 + tig * 2;
                    int r0 = mt * 16 + g;
                    float* p0 = s_H + r0 * LDH + col;
                    float* p1 = s_H + (r0 + 8) * LDH + col;
                    float* a = acc[mt * 2 + nt];
                    *(float2*)p0 = make_float2(rnd_tf32(fmaxf(a[0], 0.f)),
                                               rnd_tf32(fmaxf(a[1], 0.f)));
                    *(float2*)p1 = make_float2(rnd_tf32(fmaxf(a[2], 0.f)),
                                               rnd_tf32(fmaxf(a[3], 0.f)));
                }
        }
        __syncthreads();

        // ---- GEMM2: Wt = H @ W2 + b2, K=128 ----
        {
            float acc[16][4];
#pragma unroll
            for (int mt = 0; mt < 8; mt++)
#pragma unroll
                for (int nt = 0; nt < 2; nt++) {
                    acc[mt * 2 + nt][0] = bias2[nt * 2];
                    acc[mt * 2 + nt][1] = bias2[nt * 2 + 1];
                    acc[mt * 2 + nt][2] = bias2[nt * 2];
                    acc[mt * 2 + nt][3] = bias2[nt * 2 + 1];
                }
#pragma unroll
            for (int ks = 0; ks < 16; ks++) {
#pragma unroll
                for (int mt = 0; mt < 8; mt++) {
                    const float* ap = s_H + (mt * 16 + g) * LDH + ks * 8 + tig;
                    uint32_t a[4];
                    a[0] = __float_as_uint(ap[0]);
                    a[1] = __float_as_uint(ap[8 * LDH]);
                    a[2] = __float_as_uint(ap[4]);
                    a[3] = __float_as_uint(ap[8 * LDH + 4]);
                    mma_tf32(acc[mt * 2 + 0], a, b2f[ks][0]);
                    mma_tf32(acc[mt * 2 + 1], a, b2f[ks][1]);
                }
            }
#pragma unroll
            for (int mt = 0; mt < 8; mt++)
#pragma unroll
                for (int nt = 0; nt < 2; nt++) {
                    int col = nb + nt * 8 + tig * 2;
                    int r0 = mt * 16 + g;
                    float* a = acc[mt * 2 + nt];
                    *(float2*)(s_out + r0 * LDH + col) = make_float2(a[0], a[1]);
                    *(float2*)(s_out + (r0 + 8) * LDH + col) = make_float2(a[2], a[3]);
                }
        }
        __syncthreads();

        // ---- phase3: gather h[src], modulate, scatter-add ----
#pragma unroll 1
        for (int t = 0; t < 16; t++) {
            int e = wid * 16 + t;
            int src = s_src[e], dst = s_dst[e];
            float4 hv = *(const float4*)(h + (size_t)src * OUT_CH + lane * 4);
            float4 wv = *(const float4*)(s_out + e * LDH + lane * 4);
            red_add_v4(out + (size_t)dst * OUT_CH + lane * 4,
                       make_float4(hv.x * wv.x, hv.y * wv.y,
                                   hv.z * wv.z, hv.w * wv.w));
        }
        __syncthreads();   // protect smem buffers before next tile
    }
}

// ---------------------------------------------------------------------------
extern "C" void kernel_launch(void* const* d_in, const int* in_sizes, int n_in,
                              void* d_out, int out_size) {
    const float* x    = (const float*)d_in[0];
    const int*   eidx = (const int*)d_in[1];
    const float* rbf  = (const float*)d_in[2];
    const float* W1   = (const float*)d_in[3];
    const float* b1   = (const float*)d_in[4];
    const float* W2   = (const float*)d_in[5];
    const float* b2   = (const float*)d_in[6];
    const float* Wl   = (const float*)d_in[7];
    const float* bl   = (const float*)d_in[8];
    float* out = (float*)d_out;

    static float* h_ptr = nullptr;
    static int n_sms = 0;
    if (!h_ptr) {
        cudaGetSymbolAddress((void**)&h_ptr, g_h);
        cudaDeviceGetAttribute(&n_sms, cudaDevAttrMultiProcessorCount, 0);
        cudaFuncSetAttribute(edge_kernel_mma,
                             cudaFuncAttributeMaxDynamicSharedMemorySize, SM_BYTES);
    }

    cudaMemsetAsync(d_out, 0, (size_t)N_NODES * OUT_CH * sizeof(float), 0);
    node_linear_kernel<<<(N_NODES + 127) / 128, 256>>>(x, Wl, bl, h_ptr);
    edge_kernel_mma<<<n_sms, 256, SM_BYTES>>>(rbf, eidx, W1, b1, W2, b2,
                                              h_ptr, out, n_sms);
}

// round 5
// speedup vs baseline: 4.0054x; 1.5635x over previous
#include <cuda_runtime.h>
#include <cstdint>

#define N_NODES 40000
#define N_EDGES 640000
#define IN_CH   128
#define OUT_CH  128
#define NUM_RBF 64
#define TILE    128
#define N_TILES (N_EDGES / TILE)

// ---------------- device scratch (no allocs allowed) ----------------
__device__ float g_h[(size_t)N_NODES * OUT_CH];      // x @ Wl + bl

// ---------------- helpers ----------------
__device__ __forceinline__ float rnd_tf32(float x) {
    float r;
    asm("cvt.rna.tf32.f32 %0, %1;" : "=f"(r) : "f"(x));
    return r;
}
__device__ __forceinline__ uint32_t tf32_bits(float x) {
    return __float_as_uint(rnd_tf32(x));
}
__device__ __forceinline__ uint32_t smem_u32(const void* p) {
    uint32_t a;
    asm("{ .reg .u64 t; cvta.to.shared.u64 t, %1; cvt.u32.u64 %0, t; }"
        : "=r"(a) : "l"(p));
    return a;
}
__device__ __forceinline__ void red_add_v4(float* addr, float4 v) {
    asm volatile("red.global.add.v4.f32 [%0], {%1,%2,%3,%4};"
                 :: "l"(addr), "f"(v.x), "f"(v.y), "f"(v.z), "f"(v.w) : "memory");
}
__device__ __forceinline__ void cp16(uint32_t saddr, const void* g) {
    asm volatile("cp.async.cg.shared.global [%0], [%1], 16;"
                 :: "r"(saddr), "l"(g) : "memory");
}
__device__ __forceinline__ void cp_commit() {
    asm volatile("cp.async.commit_group;" ::: "memory");
}
__device__ __forceinline__ void cp_wait1() {
    asm volatile("cp.async.wait_group 1;" ::: "memory");
}
// mma.sync m16n8k8 tf32 (baseline PTX, sm_80+)
__device__ __forceinline__ void mma_tf32(float d[4], const uint32_t a[4],
                                         const uint32_t b[2]) {
    asm volatile(
        "mma.sync.aligned.m16n8k8.row.col.f32.tf32.tf32.f32 "
        "{%0,%1,%2,%3}, {%4,%5,%6,%7}, {%8,%9}, {%0,%1,%2,%3};"
        : "+f"(d[0]), "+f"(d[1]), "+f"(d[2]), "+f"(d[3])
        : "r"(a[0]), "r"(a[1]), "r"(a[2]), "r"(a[3]), "r"(b[0]), "r"(b[1]));
}

// ---------------------------------------------------------------------------
// node linear: h = x @ Wl + bl via tf32 mma. 128-row tile / CTA, 8 warps.
// ---------------------------------------------------------------------------
#define NL_LDX 132
#define NL_SMEM_BYTES (128 * NL_LDX * 4)

__global__ void __launch_bounds__(256)
node_linear_mma(const float* __restrict__ x, const float* __restrict__ Wl,
                const float* __restrict__ bl, float* __restrict__ h) {
    extern __shared__ float s_x[];
    const int tid = threadIdx.x;
    const int wid = tid >> 5, lane = tid & 31;
    const int g = lane >> 2, tig = lane & 3;
    const int nb = wid * 16;
    const int m0 = blockIdx.x * 128;

    // Wl fragments -> registers
    uint32_t wf[16][2][2];
#pragma unroll
    for (int ks = 0; ks < 16; ks++)
#pragma unroll
        for (int nt = 0; nt < 2; nt++) {
            int n = nb + nt * 8 + g;
            wf[ks][nt][0] = tf32_bits(Wl[(size_t)(ks * 8 + tig) * OUT_CH + n]);
            wf[ks][nt][1] = tf32_bits(Wl[(size_t)(ks * 8 + tig + 4) * OUT_CH + n]);
        }
    float bias[4];
#pragma unroll
    for (int nt = 0; nt < 2; nt++)
#pragma unroll
        for (int p = 0; p < 2; p++)
            bias[nt * 2 + p] = bl[nb + nt * 8 + tig * 2 + p];

    // x tile -> smem (tf32 rounded)
    for (int i = tid; i < 128 * 32; i += 256) {
        int r = i >> 5, q = i & 31;
        float4 v = make_float4(0.f, 0.f, 0.f, 0.f);
        if (m0 + r < N_NODES)
            v = *(const float4*)(x + (size_t)(m0 + r) * IN_CH + q * 4);
        v.x = rnd_tf32(v.x); v.y = rnd_tf32(v.y);
        v.z = rnd_tf32(v.z); v.w = rnd_tf32(v.w);
        *(float4*)(s_x + r * NL_LDX + q * 4) = v;
    }
    __syncthreads();

    float acc[16][4];
#pragma unroll
    for (int mt = 0; mt < 8; mt++)
#pragma unroll
        for (int nt = 0; nt < 2; nt++) {
            acc[mt * 2 + nt][0] = bias[nt * 2];
            acc[mt * 2 + nt][1] = bias[nt * 2 + 1];
            acc[mt * 2 + nt][2] = bias[nt * 2];
            acc[mt * 2 + nt][3] = bias[nt * 2 + 1];
        }
#pragma unroll
    for (int ks = 0; ks < 16; ks++) {
#pragma unroll
        for (int mt = 0; mt < 8; mt++) {
            const float* ap = s_x + (mt * 16 + g) * NL_LDX + ks * 8 + tig;
            uint32_t a[4];
            a[0] = __float_as_uint(ap[0]);
            a[1] = __float_as_uint(ap[8 * NL_LDX]);
            a[2] = __float_as_uint(ap[4]);
            a[3] = __float_as_uint(ap[8 * NL_LDX + 4]);
            mma_tf32(acc[mt * 2 + 0], a, wf[ks][0]);
            mma_tf32(acc[mt * 2 + 1], a, wf[ks][1]);
        }
    }
#pragma unroll
    for (int mt = 0; mt < 8; mt++)
#pragma unroll
        for (int nt = 0; nt < 2; nt++) {
            int col = nb + nt * 8 + tig * 2;
            int r0 = m0 + mt * 16 + g;
            float* a = acc[mt * 2 + nt];
            if (r0 < N_NODES)
                *(float2*)(h + (size_t)r0 * OUT_CH + col) = make_float2(a[0], a[1]);
            if (r0 + 8 < N_NODES)
                *(float2*)(h + (size_t)(r0 + 8) * OUT_CH + col) = make_float2(a[2], a[3]);
        }
}

// ---------------------------------------------------------------------------
// persistent edge kernel: cp.async double-buffered rbf/idx, tf32 mma MLP,
// batched gather + red.v4 scatter.  8 warps; warp w owns cols [w*16, w*16+16)
// ---------------------------------------------------------------------------
#define LDR 68
#define LDH 132
#define S_RBF0 0
#define S_RBF1 8704
#define S_H    17408
#define S_OUT  34304
#define S_IDX0 51200
#define S_IDX1 51456
#define S_B1   51712
#define S_B2   51840
#define SM_FLOATS 51968
#define SM_BYTES (SM_FLOATS * 4)

__device__ __forceinline__ void prefetch_tile(uint32_t sb, int buf,
                                              const float* __restrict__ rbf,
                                              const int* __restrict__ eidx,
                                              int tile, int tid) {
    const size_t e0 = (size_t)tile * TILE;
    const uint32_t rb = sb + (uint32_t)(S_RBF0 + buf * 8704) * 4u;
#pragma unroll
    for (int i = tid; i < 2048; i += 256) {
        int r = i >> 4, q = i & 15;
        cp16(rb + (uint32_t)(r * LDR + q * 4) * 4u,
             rbf + (e0 + r) * NUM_RBF + q * 4);
    }
    const uint32_t ib = sb + (uint32_t)(S_IDX0 + buf * 256) * 4u;
    if (tid < 32)
        cp16(ib + tid * 16u, eidx + e0 + tid * 4);
    else if (tid < 64)
        cp16(ib + 512u + (tid - 32) * 16u, eidx + (size_t)N_EDGES + e0 + (tid - 32) * 4);
}

__global__ void __launch_bounds__(256, 1)
edge_kernel_mma(const float* __restrict__ rbf, const int* __restrict__ eidx,
                const float* __restrict__ W1, const float* __restrict__ b1g,
                const float* __restrict__ W2, const float* __restrict__ b2g,
                const float* __restrict__ h, float* __restrict__ out,
                int grid_stride) {
    extern __shared__ float sm[];
    const uint32_t sbase = smem_u32(sm);
    float* s_H   = sm + S_H;
    float* s_out = sm + S_OUT;

    const int tid  = threadIdx.x;
    const int wid  = tid >> 5, lane = tid & 31;
    const int g    = lane >> 2, tig = lane & 3;
    const int nb   = wid * 16;

    // ---- one-time: weight fragments + biases -> registers ----
    uint32_t b1f[8][2][2];
    uint32_t b2f[16][2][2];
#pragma unroll
    for (int ks = 0; ks < 8; ks++)
#pragma unroll
        for (int nt = 0; nt < 2; nt++) {
            int n = nb + nt * 8 + g;
            b1f[ks][nt][0] = tf32_bits(W1[(size_t)(ks * 8 + tig) * OUT_CH + n]);
            b1f[ks][nt][1] = tf32_bits(W1[(size_t)(ks * 8 + tig + 4) * OUT_CH + n]);
        }
#pragma unroll
    for (int ks = 0; ks < 16; ks++)
#pragma unroll
        for (int nt = 0; nt < 2; nt++) {
            int n = nb + nt * 8 + g;
            b2f[ks][nt][0] = tf32_bits(W2[(size_t)(ks * 8 + tig) * OUT_CH + n]);
            b2f[ks][nt][1] = tf32_bits(W2[(size_t)(ks * 8 + tig + 4) * OUT_CH + n]);
        }
    float bias1[4], bias2[4];
#pragma unroll
    for (int nt = 0; nt < 2; nt++)
#pragma unroll
        for (int p = 0; p < 2; p++) {
            bias1[nt * 2 + p] = b1g[nb + nt * 8 + tig * 2 + p];
            bias2[nt * 2 + p] = b2g[nb + nt * 8 + tig * 2 + p];
        }

    // ---- prologue prefetch ----
    int buf = 0;
    prefetch_tile(sbase, 0, rbf, eidx, blockIdx.x, tid);
    cp_commit();

    for (int tile = blockIdx.x; tile < N_TILES; tile += grid_stride) {
        int nx = tile + grid_stride;
        if (nx >= N_TILES) nx = tile;                 // harmless clamp
        prefetch_tile(sbase, buf ^ 1, rbf, eidx, nx, tid);
        cp_commit();
        cp_wait1();                                   // current tile's group done
        __syncthreads();

        float* s_rbf = sm + (buf ? S_RBF1 : S_RBF0);
        int*   s_dst = (int*)(sm + (buf ? S_IDX1 : S_IDX0));
        int*   s_src = s_dst + 128;

        // ---- GEMM1: H = relu(RBF @ W1 + b1), K=64 (A truncated tf32) ----
        {
            float acc[16][4];
#pragma unroll
            for (int mt = 0; mt < 8; mt++)
#pragma unroll
                for (int nt = 0; nt < 2; nt++) {
                    acc[mt * 2 + nt][0] = bias1[nt * 2];
                    acc[mt * 2 + nt][1] = bias1[nt * 2 + 1];
                    acc[mt * 2 + nt][2] = bias1[nt * 2];
                    acc[mt * 2 + nt][3] = bias1[nt * 2 + 1];
                }
#pragma unroll
            for (int ks = 0; ks < 8; ks++) {
#pragma unroll
                for (int mt = 0; mt < 8; mt++) {
                    const float* ap = s_rbf + (mt * 16 + g) * LDR + ks * 8 + tig;
                    uint32_t a[4];
                    a[0] = __float_as_uint(ap[0]);
                    a[1] = __float_as_uint(ap[8 * LDR]);
                    a[2] = __float_as_uint(ap[4]);
                    a[3] = __float_as_uint(ap[8 * LDR + 4]);
                    mma_tf32(acc[mt * 2 + 0], a, b1f[ks][0]);
                    mma_tf32(acc[mt * 2 + 1], a, b1f[ks][1]);
                }
            }
#pragma unroll
            for (int mt = 0; mt < 8; mt++)
#pragma unroll
                for (int nt = 0; nt < 2; nt++) {
                    int col = nb + nt * 8 + tig * 2;
                    int r0 = mt * 16 + g;
                    float* a = acc[mt * 2 + nt];
                    *(float2*)(s_H + r0 * LDH + col) =
                        make_float2(rnd_tf32(fmaxf(a[0], 0.f)),
                                    rnd_tf32(fmaxf(a[1], 0.f)));
                    *(float2*)(s_H + (r0 + 8) * LDH + col) =
                        make_float2(rnd_tf32(fmaxf(a[2], 0.f)),
                                    rnd_tf32(fmaxf(a[3], 0.f)));
                }
        }
        __syncthreads();

        // ---- GEMM2: Wt = H @ W2 + b2, K=128 ----
        {
            float acc[16][4];
#pragma unroll
            for (int mt = 0; mt < 8; mt++)
#pragma unroll
                for (int nt = 0; nt < 2; nt++) {
                    acc[mt * 2 + nt][0] = bias2[nt * 2];
                    acc[mt * 2 + nt][1] = bias2[nt * 2 + 1];
                    acc[mt * 2 + nt][2] = bias2[nt * 2];
                    acc[mt * 2 + nt][3] = bias2[nt * 2 + 1];
                }
#pragma unroll
            for (int ks = 0; ks < 16; ks++) {
#pragma unroll
                for (int mt = 0; mt < 8; mt++) {
                    const float* ap = s_H + (mt * 16 + g) * LDH + ks * 8 + tig;
                    uint32_t a[4];
                    a[0] = __float_as_uint(ap[0]);
                    a[1] = __float_as_uint(ap[8 * LDH]);
                    a[2] = __float_as_uint(ap[4]);
                    a[3] = __float_as_uint(ap[8 * LDH + 4]);
                    mma_tf32(acc[mt * 2 + 0], a, b2f[ks][0]);
                    mma_tf32(acc[mt * 2 + 1], a, b2f[ks][1]);
                }
            }
#pragma unroll
            for (int mt = 0; mt < 8; mt++)
#pragma unroll
                for (int nt = 0; nt < 2; nt++) {
                    int col = nb + nt * 8 + tig * 2;
                    int r0 = mt * 16 + g;
                    float* a = acc[mt * 2 + nt];
                    *(float2*)(s_out + r0 * LDH + col) = make_float2(a[0], a[1]);
                    *(float2*)(s_out + (r0 + 8) * LDH + col) = make_float2(a[2], a[3]);
                }
        }
        __syncthreads();

        // ---- phase3: batched gather h[src] (8-deep MLP), modulate, scatter ----
#pragma unroll
        for (int half = 0; half < 2; half++) {
            float4 hv[8];
            int dst8[8];
#pragma unroll
            for (int u = 0; u < 8; u++) {
                int e = wid * 16 + half * 8 + u;
                dst8[u] = s_dst[e];
                hv[u] = *(const float4*)(h + (size_t)s_src[e] * OUT_CH + lane * 4);
            }
#pragma unroll
            for (int u = 0; u < 8; u++) {
                int e = wid * 16 + half * 8 + u;
                float4 wv = *(const float4*)(s_out + e * LDH + lane * 4);
                red_add_v4(out + (size_t)dst8[u] * OUT_CH + lane * 4,
                           make_float4(hv[u].x * wv.x, hv[u].y * wv.y,
                                       hv[u].z * wv.z, hv[u].w * wv.w));
            }
        }
        buf ^= 1;
        // no trailing sync needed: top-of-loop __syncthreads orders reuse
    }
}

// ---------------------------------------------------------------------------
extern "C" void kernel_launch(void* const* d_in, const int* in_sizes, int n_in,
                              void* d_out, int out_size) {
    const float* x    = (const float*)d_in[0];
    const int*   eidx = (const int*)d_in[1];
    const float* rbf  = (const float*)d_in[2];
    const float* W1   = (const float*)d_in[3];
    const float* b1   = (const float*)d_in[4];
    const float* W2   = (const float*)d_in[5];
    const float* b2   = (const float*)d_in[6];
    const float* Wl   = (const float*)d_in[7];
    const float* bl   = (const float*)d_in[8];
    float* out = (float*)d_out;

    static float* h_ptr = nullptr;
    static int n_sms = 0;
    if (!h_ptr) {
        cudaGetSymbolAddress((void**)&h_ptr, g_h);
        cudaDeviceGetAttribute(&n_sms, cudaDevAttrMultiProcessorCount, 0);
        cudaFuncSetAttribute(edge_kernel_mma,
                             cudaFuncAttributeMaxDynamicSharedMemorySize, SM_BYTES);
        cudaFuncSetAttribute(node_linear_mma,
                             cudaFuncAttributeMaxDynamicSharedMemorySize, NL_SMEM_BYTES);
    }

    cudaMemsetAsync(d_out, 0, (size_t)N_NODES * OUT_CH * sizeof(float), 0);
    node_linear_mma<<<(N_NODES + 127) / 128, 256, NL_SMEM_BYTES>>>(x, Wl, bl, h_ptr);
    edge_kernel_mma<<<n_sms, 256, SM_BYTES>>>(rbf, eidx, W1, b1, W2, b2,
                                              h_ptr, out, n_sms);
}

// round 7
// speedup vs baseline: 4.0085x; 1.0008x over previous
#include <cuda_runtime.h>
#include <cstdint>

#define N_NODES 40000
#define N_EDGES 640000
#define IN_CH   128
#define OUT_CH  128
#define NUM_RBF 64
#define TILE    128
#define N_TILES (N_EDGES / TILE)

// ---------------- device scratch (no allocs allowed) ----------------
__device__ float g_h[(size_t)N_NODES * OUT_CH];      // x @ Wl + bl

// ---------------- helpers ----------------
__device__ __forceinline__ float rnd_tf32(float x) {
    float r;
    asm("cvt.rna.tf32.f32 %0, %1;" : "=f"(r) : "f"(x));
    return r;
}
__device__ __forceinline__ uint32_t tf32_bits(float x) {
    return __float_as_uint(rnd_tf32(x));
}
__device__ __forceinline__ uint32_t smem_u32(const void* p) {
    uint32_t a;
    asm("{ .reg .u64 t; cvta.to.shared.u64 t, %1; cvt.u32.u64 %0, t; }"
        : "=r"(a) : "l"(p));
    return a;
}
__device__ __forceinline__ void red_add_v4(float* addr, float4 v) {
    asm volatile("red.global.add.v4.f32 [%0], {%1,%2,%3,%4};"
                 :: "l"(addr), "f"(v.x), "f"(v.y), "f"(v.z), "f"(v.w) : "memory");
}
__device__ __forceinline__ void cp16(uint32_t saddr, const void* g) {
    asm volatile("cp.async.cg.shared.global [%0], [%1], 16;"
                 :: "r"(saddr), "l"(g) : "memory");
}
__device__ __forceinline__ void cp_commit() {
    asm volatile("cp.async.commit_group;" ::: "memory");
}
__device__ __forceinline__ void cp_wait1() {
    asm volatile("cp.async.wait_group 1;" ::: "memory");
}
// mma.sync m16n8k8 tf32 (baseline PTX, sm_80+)
__device__ __forceinline__ void mma_tf32(float d[4], const uint32_t a[4],
                                         const uint32_t b[2]) {
    asm volatile(
        "mma.sync.aligned.m16n8k8.row.col.f32.tf32.tf32.f32 "
        "{%0,%1,%2,%3}, {%4,%5,%6,%7}, {%8,%9}, {%0,%1,%2,%3};"
        : "+f"(d[0]), "+f"(d[1]), "+f"(d[2]), "+f"(d[3])
        : "r"(a[0]), "r"(a[1]), "r"(a[2]), "r"(a[3]), "r"(b[0]), "r"(b[1]));
}
// ldmatrix x4: loads the 16x8-b32 A fragment (4x 8x8 b16-views)
__device__ __forceinline__ void ldsm_x4(uint32_t a[4], uint32_t saddr) {
    asm volatile("ldmatrix.sync.aligned.m8n8.x4.shared.b16 {%0,%1,%2,%3}, [%4];"
                 : "=r"(a[0]), "=r"(a[1]), "=r"(a[2]), "=r"(a[3]) : "r"(saddr));
}

// ---------------------------------------------------------------------------
// node linear: h = x @ Wl + bl via tf32 mma. 128-row tile / CTA, 8 warps.
// ---------------------------------------------------------------------------
#define NL_LDX 132
#define NL_SMEM_BYTES (128 * NL_LDX * 4)

__global__ void __launch_bounds__(256)
node_linear_mma(const float* __restrict__ x, const float* __restrict__ Wl,
                const float* __restrict__ bl, float* __restrict__ h) {
    extern __shared__ float s_x[];
    const int tid = threadIdx.x;
    const int wid = tid >> 5, lane = tid & 31;
    const int g = lane >> 2, tig = lane & 3;
    const int nb = wid * 16;
    const int m0 = blockIdx.x * 128;
    const uint32_t sx_u32 = smem_u32(s_x);
    const uint32_t a_off = ((lane & 15) * NL_LDX + ((lane >> 4) << 2)) * 4u;

    uint32_t wf[16][2][2];
#pragma unroll
    for (int ks = 0; ks < 16; ks++)
#pragma unroll
        for (int nt = 0; nt < 2; nt++) {
            int n = nb + nt * 8 + g;
            wf[ks][nt][0] = tf32_bits(Wl[(size_t)(ks * 8 + tig) * OUT_CH + n]);
            wf[ks][nt][1] = tf32_bits(Wl[(size_t)(ks * 8 + tig + 4) * OUT_CH + n]);
        }
    float bias[4];
#pragma unroll
    for (int nt = 0; nt < 2; nt++)
#pragma unroll
        for (int p = 0; p < 2; p++)
            bias[nt * 2 + p] = bl[nb + nt * 8 + tig * 2 + p];

    for (int i = tid; i < 128 * 32; i += 256) {
        int r = i >> 5, q = i & 31;
        float4 v = make_float4(0.f, 0.f, 0.f, 0.f);
        if (m0 + r < N_NODES)
            v = *(const float4*)(x + (size_t)(m0 + r) * IN_CH + q * 4);
        v.x = rnd_tf32(v.x); v.y = rnd_tf32(v.y);
        v.z = rnd_tf32(v.z); v.w = rnd_tf32(v.w);
        *(float4*)(s_x + r * NL_LDX + q * 4) = v;
    }
    __syncthreads();

    float acc[16][4];
#pragma unroll
    for (int mt = 0; mt < 8; mt++)
#pragma unroll
        for (int nt = 0; nt < 2; nt++) {
            acc[mt * 2 + nt][0] = bias[nt * 2];
            acc[mt * 2 + nt][1] = bias[nt * 2 + 1];
            acc[mt * 2 + nt][2] = bias[nt * 2];
            acc[mt * 2 + nt][3] = bias[nt * 2 + 1];
        }
#pragma unroll
    for (int ks = 0; ks < 16; ks++) {
#pragma unroll
        for (int mt = 0; mt < 8; mt++) {
            uint32_t a[4];
            ldsm_x4(a, sx_u32 + (uint32_t)(mt * 16 * NL_LDX + ks * 8) * 4u + a_off);
            mma_tf32(acc[mt * 2 + 0], a, wf[ks][0]);
            mma_tf32(acc[mt * 2 + 1], a, wf[ks][1]);
        }
    }
#pragma unroll
    for (int mt = 0; mt < 8; mt++)
#pragma unroll
        for (int nt = 0; nt < 2; nt++) {
            int col = nb + nt * 8 + tig * 2;
            int r0 = m0 + mt * 16 + g;
            float* a = acc[mt * 2 + nt];
            if (r0 < N_NODES)
                *(float2*)(h + (size_t)r0 * OUT_CH + col) = make_float2(a[0], a[1]);
            if (r0 + 8 < N_NODES)
                *(float2*)(h + (size_t)(r0 + 8) * OUT_CH + col) = make_float2(a[2], a[3]);
        }
}

// ---------------------------------------------------------------------------
// persistent edge kernel
//   GEMM1: 8 warps x (M=128, N=16)   — b1f in regs (32)
//   GEMM2: warps as 2M x 4N (M=64, N=32 each) — b2f in regs (128)
//   ldmatrix for all A fragments; cp.async double-buffered rbf/idx
//   trailing __syncthreads closes the phase3-vs-prefetch race (R6 bug)
// ---------------------------------------------------------------------------
#define LDR 68
#define LDH 132
#define S_RBF0 0
#define S_RBF1 8704
#define S_H    17408
#define S_OUT  34304
#define S_IDX0 51200
#define S_IDX1 51456
#define S_B1   51712
#define S_B2   51840
#define SM_FLOATS 51968
#define SM_BYTES (SM_FLOATS * 4)

__device__ __forceinline__ void prefetch_tile(uint32_t sb, int buf,
                                              const float* __restrict__ rbf,
                                              const int* __restrict__ eidx,
                                              int tile, int tid) {
    const size_t e0 = (size_t)tile * TILE;
    const uint32_t rb = sb + (uint32_t)(S_RBF0 + buf * 8704) * 4u;
#pragma unroll
    for (int i = tid; i < 2048; i += 256) {
        int r = i >> 4, q = i & 15;
        cp16(rb + (uint32_t)(r * LDR + q * 4) * 4u,
             rbf + (e0 + r) * NUM_RBF + q * 4);
    }
    const uint32_t ib = sb + (uint32_t)(S_IDX0 + buf * 256) * 4u;
    if (tid < 32)
        cp16(ib + tid * 16u, eidx + e0 + tid * 4);
    else if (tid < 64)
        cp16(ib + 512u + (tid - 32) * 16u, eidx + (size_t)N_EDGES + e0 + (tid - 32) * 4);
}

__global__ void __launch_bounds__(256, 1)
edge_kernel_mma(const float* __restrict__ rbf, const int* __restrict__ eidx,
                const float* __restrict__ W1, const float* __restrict__ b1g,
                const float* __restrict__ W2, const float* __restrict__ b2g,
                const float* __restrict__ h, float* __restrict__ out,
                int grid_stride) {
    extern __shared__ float sm[];
    const uint32_t sbase = smem_u32(sm);
    float* s_H   = sm + S_H;
    float* s_out = sm + S_OUT;
    float* s_b1  = sm + S_B1;
    float* s_b2  = sm + S_B2;

    const int tid  = threadIdx.x;
    const int wid  = tid >> 5, lane = tid & 31;
    const int g    = lane >> 2, tig = lane & 3;
    const int nb   = wid * 16;          // GEMM1 N base
    const int mg   = wid >> 2;          // GEMM2 M group (0..1)
    const int ng   = wid & 3;           // GEMM2 N group (0..3)

    const uint32_t aoff_r = ((lane & 15) * LDR + ((lane >> 4) << 2)) * 4u;
    const uint32_t aoff_h = ((lane & 15) * LDH + ((lane >> 4) << 2)) * 4u;
    const uint32_t sH_u32 = sbase + (uint32_t)S_H * 4u;

    // ---- one-time: weight fragments -> registers; biases -> smem ----
    uint32_t b1f[8][2][2];
#pragma unroll
    for (int ks = 0; ks < 8; ks++)
#pragma unroll
        for (int nt = 0; nt < 2; nt++) {
            int n = nb + nt * 8 + g;
            b1f[ks][nt][0] = tf32_bits(W1[(size_t)(ks * 8 + tig) * OUT_CH + n]);
            b1f[ks][nt][1] = tf32_bits(W1[(size_t)(ks * 8 + tig + 4) * OUT_CH + n]);
        }
    uint32_t b2f[16][4][2];
#pragma unroll
    for (int ks = 0; ks < 16; ks++)
#pragma unroll
        for (int n8 = 0; n8 < 4; n8++) {
            int n = ng * 32 + n8 * 8 + g;
            b2f[ks][n8][0] = tf32_bits(W2[(size_t)(ks * 8 + tig) * OUT_CH + n]);
            b2f[ks][n8][1] = tf32_bits(W2[(size_t)(ks * 8 + tig + 4) * OUT_CH + n]);
        }
    if (tid < 128) { s_b1[tid] = b1g[tid]; s_b2[tid] = b2g[tid]; }

    // ---- prologue prefetch ----
    int buf = 0;
    prefetch_tile(sbase, 0, rbf, eidx, blockIdx.x, tid);
    cp_commit();

    for (int tile = blockIdx.x; tile < N_TILES; tile += grid_stride) {
        int nx = tile + grid_stride;
        if (nx >= N_TILES) nx = tile;
        prefetch_tile(sbase, buf ^ 1, rbf, eidx, nx, tid);
        cp_commit();
        cp_wait1();
        __syncthreads();

        const uint32_t sR_u32 = sbase + (uint32_t)(S_RBF0 + buf * 8704) * 4u;
        int* s_dst = (int*)(sm + (buf ? S_IDX1 : S_IDX0));
        int* s_src = s_dst + 128;

        // ---- GEMM1: H = relu(RBF @ W1 + b1), 8 warps x N16, K=64 ----
        {
            float acc[16][4];
#pragma unroll
            for (int q = 0; q < 16; q++)
#pragma unroll
                for (int p = 0; p < 4; p++) acc[q][p] = 0.f;
#pragma unroll
            for (int ks = 0; ks < 8; ks++) {
#pragma unroll
                for (int mt = 0; mt < 8; mt++) {
                    uint32_t a[4];
                    ldsm_x4(a, sR_u32 + (uint32_t)(mt * 16 * LDR + ks * 8) * 4u + aoff_r);
                    mma_tf32(acc[mt * 2 + 0], a, b1f[ks][0]);
                    mma_tf32(acc[mt * 2 + 1], a, b1f[ks][1]);
                }
            }
#pragma unroll
            for (int nt = 0; nt < 2; nt++) {
                int col = nb + nt * 8 + tig * 2;
                float2 bz = *(const float2*)(s_b1 + col);
#pragma unroll
                for (int mt = 0; mt < 8; mt++) {
                    int r0 = mt * 16 + g;
                    float* a = acc[mt * 2 + nt];
                    *(float2*)(s_H + r0 * LDH + col) =
                        make_float2(rnd_tf32(fmaxf(a[0] + bz.x, 0.f)),
                                    rnd_tf32(fmaxf(a[1] + bz.y, 0.f)));
                    *(float2*)(s_H + (r0 + 8) * LDH + col) =
                        make_float2(rnd_tf32(fmaxf(a[2] + bz.x, 0.f)),
                                    rnd_tf32(fmaxf(a[3] + bz.y, 0.f)));
                }
            }
        }
        __syncthreads();

        // ---- GEMM2: Wt = H @ W2 + b2, warps 2M x 4N (M=64, N=32), K=128 ----
        {
            float acc[16][4];   // [mt*4 + n8]
#pragma unroll
            for (int q = 0; q < 16; q++)
#pragma unroll
                for (int p = 0; p < 4; p++) acc[q][p] = 0.f;
#pragma unroll
            for (int ks = 0; ks < 16; ks++) {
#pragma unroll
                for (int mt = 0; mt < 4; mt++) {
                    uint32_t a[4];
                    ldsm_x4(a, sH_u32 +
                            (uint32_t)((mg * 64 + mt * 16) * LDH + ks * 8) * 4u + aoff_h);
#pragma unroll
                    for (int n8 = 0; n8 < 4; n8++)
                        mma_tf32(acc[mt * 4 + n8], a, b2f[ks][n8]);
                }
            }
#pragma unroll
            for (int n8 = 0; n8 < 4; n8++) {
                int col = ng * 32 + n8 * 8 + tig * 2;
                float2 bz = *(const float2*)(s_b2 + col);
#pragma unroll
                for (int mt = 0; mt < 4; mt++) {
                    int r0 = mg * 64 + mt * 16 + g;
                    float* a = acc[mt * 4 + n8];
                    *(float2*)(s_out + r0 * LDH + col) =
                        make_float2(a[0] + bz.x, a[1] + bz.y);
                    *(float2*)(s_out + (r0 + 8) * LDH + col) =
                        make_float2(a[2] + bz.x, a[3] + bz.y);
                }
            }
        }
        __syncthreads();

        // ---- phase3: batched gather h[src], modulate, red.v4 scatter ----
#pragma unroll
        for (int half = 0; half < 2; half++) {
            float4 hv[8];
            int dst8[8];
#pragma unroll
            for (int u = 0; u < 8; u++) {
                int e = wid * 16 + half * 8 + u;
                dst8[u] = s_dst[e];
                hv[u] = *(const float4*)(h + (size_t)s_src[e] * OUT_CH + lane * 4);
            }
#pragma unroll
            for (int u = 0; u < 8; u++) {
                int e = wid * 16 + half * 8 + u;
                float4 wv = *(const float4*)(s_out + e * LDH + lane * 4);
                red_add_v4(out + (size_t)dst8[u] * OUT_CH + lane * 4,
                           make_float4(hv[u].x * wv.x, hv[u].y * wv.y,
                                       hv[u].z * wv.z, hv[u].w * wv.w));
            }
        }
        // RACE FIX (R6 post-mortem): all warps must finish reading this tile's
        // idx/rbf buffers before the next iteration's cp.async overwrites them.
        __syncthreads();
        buf ^= 1;
    }
}

// ---------------------------------------------------------------------------
extern "C" void kernel_launch(void* const* d_in, const int* in_sizes, int n_in,
                              void* d_out, int out_size) {
    const float* x    = (const float*)d_in[0];
    const int*   eidx = (const int*)d_in[1];
    const float* rbf  = (const float*)d_in[2];
    const float* W1   = (const float*)d_in[3];
    const float* b1   = (const float*)d_in[4];
    const float* W2   = (const float*)d_in[5];
    const float* b2   = (const float*)d_in[6];
    const float* Wl   = (const float*)d_in[7];
    const float* bl   = (const float*)d_in[8];
    float* out = (float*)d_out;

    static float* h_ptr = nullptr;
    static int n_sms = 0;
    if (!h_ptr) {
        cudaGetSymbolAddress((void**)&h_ptr, g_h);
        cudaDeviceGetAttribute(&n_sms, cudaDevAttrMultiProcessorCount, 0);
        cudaFuncSetAttribute(edge_kernel_mma,
                             cudaFuncAttributeMaxDynamicSharedMemorySize, SM_BYTES);
        cudaFuncSetAttribute(node_linear_mma,
                             cudaFuncAttributeMaxDynamicSharedMemorySize, NL_SMEM_BYTES);
    }

    cudaMemsetAsync(d_out, 0, (size_t)N_NODES * OUT_CH * sizeof(float), 0);
    node_linear_mma<<<(N_NODES + 127) / 128, 256, NL_SMEM_BYTES>>>(x, Wl, bl, h_ptr);
    edge_kernel_mma<<<n_sms, 256, SM_BYTES>>>(rbf, eidx, W1, b1, W2, b2,
                                              h_ptr, out, n_sms);
}

// round 8
// speedup vs baseline: 4.1258x; 1.0293x over previous
#include <cuda_runtime.h>
#include <cstdint>

#define N_NODES 40000
#define N_EDGES 640000
#define IN_CH   128
#define OUT_CH  128
#define NUM_RBF 64
#define TILE64  64
#define NT64    (N_EDGES / TILE64)     // 10000

// ---------------- device scratch (no allocs allowed) ----------------
__device__ float g_h[(size_t)N_NODES * OUT_CH];      // x @ Wl + bl

// ---------------- helpers ----------------
__device__ __forceinline__ float rnd_tf32(float x) {
    float r;
    asm("cvt.rna.tf32.f32 %0, %1;" : "=f"(r) : "f"(x));
    return r;
}
__device__ __forceinline__ uint32_t tf32_bits(float x) {
    return __float_as_uint(rnd_tf32(x));
}
__device__ __forceinline__ uint32_t smem_u32(const void* p) {
    uint32_t a;
    asm("{ .reg .u64 t; cvta.to.shared.u64 t, %1; cvt.u32.u64 %0, t; }"
        : "=r"(a) : "l"(p));
    return a;
}
__device__ __forceinline__ void red_add_v4(float* addr, float4 v) {
    asm volatile("red.global.add.v4.f32 [%0], {%1,%2,%3,%4};"
                 :: "l"(addr), "f"(v.x), "f"(v.y), "f"(v.z), "f"(v.w) : "memory");
}
__device__ __forceinline__ void cp16(uint32_t saddr, const void* g) {
    asm volatile("cp.async.cg.shared.global [%0], [%1], 16;"
                 :: "r"(saddr), "l"(g) : "memory");
}
__device__ __forceinline__ void cp_commit() {
    asm volatile("cp.async.commit_group;" ::: "memory");
}
__device__ __forceinline__ void cp_wait1() {
    asm volatile("cp.async.wait_group 1;" ::: "memory");
}
__device__ __forceinline__ void bar_grp(int id) {
    asm volatile("bar.sync %0, 128;" :: "r"(id) : "memory");
}
__device__ __forceinline__ void l2_prefetch(const float* p) {
    asm volatile("prefetch.global.L2 [%0];" :: "l"(p));
}
// mma.sync m16n8k8 tf32 (baseline PTX, sm_80+)
__device__ __forceinline__ void mma_tf32(float d[4], const uint32_t a[4],
                                         const uint32_t b[2]) {
    asm volatile(
        "mma.sync.aligned.m16n8k8.row.col.f32.tf32.tf32.f32 "
        "{%0,%1,%2,%3}, {%4,%5,%6,%7}, {%8,%9}, {%0,%1,%2,%3};"
        : "+f"(d[0]), "+f"(d[1]), "+f"(d[2]), "+f"(d[3])
        : "r"(a[0]), "r"(a[1]), "r"(a[2]), "r"(a[3]), "r"(b[0]), "r"(b[1]));
}
__device__ __forceinline__ void ldsm_x4(uint32_t a[4], uint32_t saddr) {
    asm volatile("ldmatrix.sync.aligned.m8n8.x4.shared.b16 {%0,%1,%2,%3}, [%4];"
                 : "=r"(a[0]), "=r"(a[1]), "=r"(a[2]), "=r"(a[3]) : "r"(saddr));
}

// ---------------------------------------------------------------------------
// node linear: h = x @ Wl + bl via tf32 mma (unchanged from R7)
// ---------------------------------------------------------------------------
#define NL_LDX 132
#define NL_SMEM_BYTES (128 * NL_LDX * 4)

__global__ void __launch_bounds__(256)
node_linear_mma(const float* __restrict__ x, const float* __restrict__ Wl,
                const float* __restrict__ bl, float* __restrict__ h) {
    extern __shared__ float s_x[];
    const int tid = threadIdx.x;
    const int wid = tid >> 5, lane = tid & 31;
    const int qr = lane >> 2, tig = lane & 3;
    const int nb = wid * 16;
    const int m0 = blockIdx.x * 128;
    const uint32_t sx_u32 = smem_u32(s_x);
    const uint32_t a_off = ((lane & 15) * NL_LDX + ((lane >> 4) << 2)) * 4u;

    uint32_t wf[16][2][2];
#pragma unroll
    for (int ks = 0; ks < 16; ks++)
#pragma unroll
        for (int nt = 0; nt < 2; nt++) {
            int n = nb + nt * 8 + qr;
            wf[ks][nt][0] = tf32_bits(Wl[(size_t)(ks * 8 + tig) * OUT_CH + n]);
            wf[ks][nt][1] = tf32_bits(Wl[(size_t)(ks * 8 + tig + 4) * OUT_CH + n]);
        }
    float bias[4];
#pragma unroll
    for (int nt = 0; nt < 2; nt++)
#pragma unroll
        for (int p = 0; p < 2; p++)
            bias[nt * 2 + p] = bl[nb + nt * 8 + tig * 2 + p];

    for (int i = tid; i < 128 * 32; i += 256) {
        int r = i >> 5, q = i & 31;
        float4 v = make_float4(0.f, 0.f, 0.f, 0.f);
        if (m0 + r < N_NODES)
            v = *(const float4*)(x + (size_t)(m0 + r) * IN_CH + q * 4);
        v.x = rnd_tf32(v.x); v.y = rnd_tf32(v.y);
        v.z = rnd_tf32(v.z); v.w = rnd_tf32(v.w);
        *(float4*)(s_x + r * NL_LDX + q * 4) = v;
    }
    __syncthreads();

    float acc[16][4];
#pragma unroll
    for (int mt = 0; mt < 8; mt++)
#pragma unroll
        for (int nt = 0; nt < 2; nt++) {
            acc[mt * 2 + nt][0] = bias[nt * 2];
            acc[mt * 2 + nt][1] = bias[nt * 2 + 1];
            acc[mt * 2 + nt][2] = bias[nt * 2];
            acc[mt * 2 + nt][3] = bias[nt * 2 + 1];
        }
#pragma unroll
    for (int ks = 0; ks < 16; ks++) {
#pragma unroll
        for (int mt = 0; mt < 8; mt++) {
            uint32_t a[4];
            ldsm_x4(a, sx_u32 + (uint32_t)(mt * 16 * NL_LDX + ks * 8) * 4u + a_off);
            mma_tf32(acc[mt * 2 + 0], a, wf[ks][0]);
            mma_tf32(acc[mt * 2 + 1], a, wf[ks][1]);
        }
    }
#pragma unroll
    for (int mt = 0; mt < 8; mt++)
#pragma unroll
        for (int nt = 0; nt < 2; nt++) {
            int col = nb + nt * 8 + tig * 2;
            int r0 = m0 + mt * 16 + qr;
            float* a = acc[mt * 2 + nt];
            if (r0 < N_NODES)
                *(float2*)(h + (size_t)r0 * OUT_CH + col) = make_float2(a[0], a[1]);
            if (r0 + 8 < N_NODES)
                *(float2*)(h + (size_t)(r0 + 8) * OUT_CH + col) = make_float2(a[2], a[3]);
        }
}

// ---------------------------------------------------------------------------
// persistent edge kernel: TWO independent 4-warp groups per CTA.
// Group g (warps 4g..4g+3) processes its own stream of 64-edge tiles with
// private smem + named barrier (1+g). Sub-passed GEMMs keep regs <= ~245.
//
// Per-group smem (floats): rbf0 4352 | rbf1 4352 | H 8448 | OUT 8448 |
//                          idx0 128 | idx1 128   == 25856
// Globals: b1 128 | b2 128.  Total 51968 floats = 207,872 B.
// ---------------------------------------------------------------------------
#define LDR 68
#define LDH 132
#define GRP_FLOATS 25856
#define G_RBF  0
#define G_H    8704
#define G_OUT  17152
#define G_IDX  25600
#define S_B1   (2 * GRP_FLOATS)          // 51712
#define S_B2   (S_B1 + 128)
#define SM_FLOATS (S_B2 + 128)
#define SM_BYTES  (SM_FLOATS * 4)

__device__ __forceinline__ void prefetch64(uint32_t g_u32, int buf,
                                           const float* __restrict__ rbf,
                                           const int* __restrict__ eidx,
                                           int tile, int tidg) {
    const size_t e0 = (size_t)tile * TILE64;
    const uint32_t rb = g_u32 + (uint32_t)(G_RBF + buf * 4352) * 4u;
#pragma unroll
    for (int i = tidg; i < 1024; i += 128) {
        int r = i >> 4, q = i & 15;
        cp16(rb + (uint32_t)(r * LDR + q * 4) * 4u,
             rbf + (e0 + r) * NUM_RBF + q * 4);
    }
    const uint32_t ib = g_u32 + (uint32_t)(G_IDX + buf * 128) * 4u;
    if (tidg < 16)
        cp16(ib + tidg * 16u, eidx + e0 + tidg * 4);
    else if (tidg < 32)
        cp16(ib + 256u + (tidg - 16) * 16u,
             eidx + (size_t)N_EDGES + e0 + (tidg - 16) * 4);
}

__global__ void __launch_bounds__(256, 1)
edge_kernel_grp(const float* __restrict__ rbf, const int* __restrict__ eidx,
                const float* __restrict__ W1, const float* __restrict__ b1g,
                const float* __restrict__ W2, const float* __restrict__ b2g,
                const float* __restrict__ h, float* __restrict__ out,
                int n_ctas) {
    extern __shared__ float sm[];
    const uint32_t sbase = smem_u32(sm);
    const int tid  = threadIdx.x;
    const int wid  = tid >> 5, lane = tid & 31;
    const int grp  = wid >> 2;           // 0 or 1
    const int wg   = wid & 3;            // warp within group
    const int tidg = tid & 127;
    const int qr   = lane >> 2, tig = lane & 3;
    const int wn   = wg * 32;            // warp's N base (both GEMMs)
    const int barid = 1 + grp;

    const int GRP = grp * GRP_FLOATS;
    float* s_H   = sm + GRP + G_H;
    float* s_out = sm + GRP + G_OUT;
    float* s_b1  = sm + S_B1;
    float* s_b2  = sm + S_B2;

    const uint32_t g_u32  = sbase + (uint32_t)GRP * 4u;
    const uint32_t sH_u32 = g_u32 + (uint32_t)G_H * 4u;
    const uint32_t aoff_r = ((lane & 15) * LDR + ((lane >> 4) << 2)) * 4u;
    const uint32_t aoff_h = ((lane & 15) * LDH + ((lane >> 4) << 2)) * 4u;

    // ---- one-time: weight fragments -> regs (N=32 per warp), biases -> smem
    uint32_t b1f[8][4][2];               // 64 regs
#pragma unroll
    for (int ks = 0; ks < 8; ks++)
#pragma unroll
        for (int n8 = 0; n8 < 4; n8++) {
            int n = wn + n8 * 8 + qr;
            b1f[ks][n8][0] = tf32_bits(W1[(size_t)(ks * 8 + tig) * OUT_CH + n]);
            b1f[ks][n8][1] = tf32_bits(W1[(size_t)(ks * 8 + tig + 4) * OUT_CH + n]);
        }
    uint32_t b2f[16][4][2];              // 128 regs
#pragma unroll
    for (int ks = 0; ks < 16; ks++)
#pragma unroll
        for (int n8 = 0; n8 < 4; n8++) {
            int n = wn + n8 * 8 + qr;
            b2f[ks][n8][0] = tf32_bits(W2[(size_t)(ks * 8 + tig) * OUT_CH + n]);
            b2f[ks][n8][1] = tf32_bits(W2[(size_t)(ks * 8 + tig + 4) * OUT_CH + n]);
        }
    if (tid < 128) { s_b1[tid] = b1g[tid]; s_b2[tid] = b2g[tid]; }
    __syncthreads();                     // last CTA-wide barrier; groups diverge now

    const int start = blockIdx.x * 2 + grp;
    const int step  = n_ctas * 2;
    int buf = 0;
    prefetch64(g_u32, 0, rbf, eidx, start, tidg);
    cp_commit();

    for (int tile = start; tile < NT64; tile += step) {
        int nx = tile + step;
        if (nx >= NT64) nx = tile;
        prefetch64(g_u32, buf ^ 1, rbf, eidx, nx, tidg);
        cp_commit();
        cp_wait1();
        bar_grp(barid);

        int* s_dst = (int*)(sm + GRP + G_IDX + buf * 128);
        int* s_src = s_dst + 64;

        // L2-prefetch this tile's h rows (2 GEMMs of lead time).
        {
            int e = wg * 16 + (lane >> 1);
            const float* p = h + (size_t)s_src[e] * OUT_CH + (lane & 1) * 32;
            l2_prefetch(p);
            l2_prefetch(p + 64);
        }

        const uint32_t sR = g_u32 + (uint32_t)(G_RBF + buf * 4352) * 4u;

        // ---- GEMM1: H = relu(RBF @ W1 + b1); M=64, warp N=32, 2 sub-passes
#pragma unroll
        for (int p = 0; p < 2; p++) {
            float acc[4][2][4];
#pragma unroll
            for (int mt = 0; mt < 4; mt++)
#pragma unroll
                for (int j = 0; j < 2; j++)
#pragma unroll
                    for (int q = 0; q < 4; q++) acc[mt][j][q] = 0.f;
#pragma unroll
            for (int ks = 0; ks < 8; ks++)
#pragma unroll
                for (int mt = 0; mt < 4; mt++) {
                    uint32_t a[4];
                    ldsm_x4(a, sR + (uint32_t)(mt * 16 * LDR + ks * 8) * 4u + aoff_r);
                    mma_tf32(acc[mt][0], a, b1f[ks][2 * p + 0]);
                    mma_tf32(acc[mt][1], a, b1f[ks][2 * p + 1]);
                }
#pragma unroll
            for (int j = 0; j < 2; j++) {
                int col = wn + (2 * p + j) * 8 + tig * 2;
                float2 bz = *(const float2*)(s_b1 + col);
#pragma unroll
                for (int mt = 0; mt < 4; mt++) {
                    int r0 = mt * 16 + qr;
                    float* a = acc[mt][j];
                    *(float2*)(s_H + r0 * LDH + col) =
                        make_float2(rnd_tf32(fmaxf(a[0] + bz.x, 0.f)),
                                    rnd_tf32(fmaxf(a[1] + bz.y, 0.f)));
                    *(float2*)(s_H + (r0 + 8) * LDH + col) =
                        make_float2(rnd_tf32(fmaxf(a[2] + bz.x, 0.f)),
                                    rnd_tf32(fmaxf(a[3] + bz.y, 0.f)));
                }
            }
        }
        bar_grp(barid);

        // ---- GEMM2: Wt = H @ W2 + b2; M=64, warp N=32, 2 sub-passes, K=128
#pragma unroll
        for (int p = 0; p < 2; p++) {
            float acc[4][2][4];
#pragma unroll
            for (int mt = 0; mt < 4; mt++)
#pragma unroll
                for (int j = 0; j < 2; j++)
#pragma unroll
                    for (int q = 0; q < 4; q++) acc[mt][j][q] = 0.f;
#pragma unroll
            for (int ks = 0; ks < 16; ks++)
#pragma unroll
                for (int mt = 0; mt < 4; mt++) {
                    uint32_t a[4];
                    ldsm_x4(a, sH_u32 + (uint32_t)(mt * 16 * LDH + ks * 8) * 4u + aoff_h);
                    mma_tf32(acc[mt][0], a, b2f[ks][2 * p + 0]);
                    mma_tf32(acc[mt][1], a, b2f[ks][2 * p + 1]);
                }
#pragma unroll
            for (int j = 0; j < 2; j++) {
                int col = wn + (2 * p + j) * 8 + tig * 2;
                float2 bz = *(const float2*)(s_b2 + col);
#pragma unroll
                for (int mt = 0; mt < 4; mt++) {
                    int r0 = mt * 16 + qr;
                    float* a = acc[mt][j];
                    *(float2*)(s_out + r0 * LDH + col) =
                        make_float2(a[0] + bz.x, a[1] + bz.y);
                    *(float2*)(s_out + (r0 + 8) * LDH + col) =
                        make_float2(a[2] + bz.x, a[3] + bz.y);
                }
            }
        }
        bar_grp(barid);

        // ---- phase3: warp owns 16 edges; batched gather, red.v4 scatter
#pragma unroll
        for (int half = 0; half < 2; half++) {
            float4 hv[8];
            int dst8[8];
#pragma unroll
            for (int u = 0; u < 8; u++) {
                int e = wg * 16 + half * 8 + u;
                dst8[u] = s_dst[e];
                hv[u] = *(const float4*)(h + (size_t)s_src[e] * OUT_CH + lane * 4);
            }
#pragma unroll
            for (int u = 0; u < 8; u++) {
                int e = wg * 16 + half * 8 + u;
                float4 wv = *(const float4*)(s_out + e * LDH + lane * 4);
                red_add_v4(out + (size_t)dst8[u] * OUT_CH + lane * 4,
                           make_float4(hv[u].x * wv.x, hv[u].y * wv.y,
                                       hv[u].z * wv.z, hv[u].w * wv.w));
            }
        }
        // Race guard (R6 lesson): next iteration's cp.async overwrites THIS
        // buffer's rbf/idx; all group warps must be done reading first.
        bar_grp(barid);
        buf ^= 1;
    }
}

// ---------------------------------------------------------------------------
extern "C" void kernel_launch(void* const* d_in, const int* in_sizes, int n_in,
                              void* d_out, int out_size) {
    const float* x    = (const float*)d_in[0];
    const int*   eidx = (const int*)d_in[1];
    const float* rbf  = (const float*)d_in[2];
    const float* W1   = (const float*)d_in[3];
    const float* b1   = (const float*)d_in[4];
    const float* W2   = (const float*)d_in[5];
    const float* b2   = (const float*)d_in[6];
    const float* Wl   = (const float*)d_in[7];
    const float* bl   = (const float*)d_in[8];
    float* out = (float*)d_out;

    static float* h_ptr = nullptr;
    static int n_sms = 0;
    if (!h_ptr) {
        cudaGetSymbolAddress((void**)&h_ptr, g_h);
        cudaDeviceGetAttribute(&n_sms, cudaDevAttrMultiProcessorCount, 0);
        cudaFuncSetAttribute(edge_kernel_grp,
                             cudaFuncAttributeMaxDynamicSharedMemorySize, SM_BYTES);
        cudaFuncSetAttribute(node_linear_mma,
                             cudaFuncAttributeMaxDynamicSharedMemorySize, NL_SMEM_BYTES);
    }

    cudaMemsetAsync(d_out, 0, (size_t)N_NODES * OUT_CH * sizeof(float), 0);
    node_linear_mma<<<(N_NODES + 127) / 128, 256, NL_SMEM_BYTES>>>(x, Wl, bl, h_ptr);
    edge_kernel_grp<<<n_sms, 256, SM_BYTES>>>(rbf, eidx, W1, b1, W2, b2,
                                              h_ptr, out, n_sms);
}